// round 8
// baseline (speedup 1.0000x reference)
#include <cuda_runtime.h>
#include <cuda_bf16.h>
#include <cuda_fp16.h>
#include <cstdint>

#define NN 50000
#define EE 800000
#define RR 4
#define GG 16
#define MT 782   // ceil(NN/64) M-tiles

// ---------------- scratch (device globals; no allocation) ----------------
__device__ float   g_Ys[NN * 128];          // self+bias, fp32 [N][out]
__device__ __half  g_Ym[NN * 512];          // messages fp16 [N][4*out] (L2-resident)
__device__ __half  g_Asp[NN * 128];         // activations fp16 [N][128]
__device__ __half  g_Bsp[128 * 640];        // weights fp16, row-major [k][5*out]
__device__ float   g_q[GG * 64];
__device__ int     g_cnt[RR * NN];
__device__ float   g_inv[NN * 4];
__device__ int     g_deg[NN];
__device__ int     g_part[256];
__device__ int     g_rowptr[NN + 1];
__device__ int     g_fill[NN];
__device__ int     g_csr[EE];               // src | (rel<<28)

// ---------------- helpers ----------------
__device__ __forceinline__ uint32_t smem_u32(const void* p) {
    return (uint32_t)__cvta_generic_to_shared(p);
}
__device__ __forceinline__ void ldsm4(uint32_t* d, const __half* p) {
    uint32_t a = smem_u32(p);
    asm volatile("ldmatrix.sync.aligned.m8n8.x4.shared.b16 {%0,%1,%2,%3}, [%4];"
                 : "=r"(d[0]), "=r"(d[1]), "=r"(d[2]), "=r"(d[3]) : "r"(a));
}
__device__ __forceinline__ void ldsm4t(uint32_t* d, const __half* p) {
    uint32_t a = smem_u32(p);
    asm volatile("ldmatrix.sync.aligned.m8n8.x4.trans.shared.b16 {%0,%1,%2,%3}, [%4];"
                 : "=r"(d[0]), "=r"(d[1]), "=r"(d[2]), "=r"(d[3]) : "r"(a));
}
__device__ __forceinline__ void mma16816(float* c, const uint32_t* a, uint32_t b0, uint32_t b1) {
    asm volatile(
        "mma.sync.aligned.m16n8k16.row.col.f32.f16.f16.f32 "
        "{%0,%1,%2,%3}, {%4,%5,%6,%7}, {%8,%9}, {%0,%1,%2,%3};"
        : "+f"(c[0]), "+f"(c[1]), "+f"(c[2]), "+f"(c[3])
        : "r"(a[0]), "r"(a[1]), "r"(a[2]), "r"(a[3]), "r"(b0), "r"(b1));
}
__device__ __forceinline__ void cp_async16(uint32_t smem_addr, const void* gptr) {
    asm volatile("cp.async.cg.shared.global [%0], [%1], 16;" :: "r"(smem_addr), "l"(gptr));
}
__device__ __forceinline__ void cp_commit() {
    asm volatile("cp.async.commit_group;" ::: "memory");
}
template <int N>
__device__ __forceinline__ void cp_wait() {
    asm volatile("cp.async.wait_group %0;" :: "n"(N) : "memory");
}
__device__ __forceinline__ float pick4(float4 v, int r) {
    return r == 0 ? v.x : (r == 1 ? v.y : (r == 2 ? v.z : v.w));
}

// ---------------- layer-0 activation fp16 from x (+ zero g_cnt) ----------------
__global__ void k_prepA0(const float* __restrict__ x) {
    int idx = blockIdx.x * blockDim.x + threadIdx.x;
    if (idx < RR * NN) g_cnt[idx] = 0;
    if (idx >= NN * 128) return;
    g_Asp[idx] = __float2half_rn(x[idx]);
}

// ---------------- weight concat fp16: B[k][5*out] ----------------
__global__ void k_prepB(const float* __restrict__ root, const float* __restrict__ W, int out) {
    int ncols = 5 * out;
    int idx = blockIdx.x * blockDim.x + threadIdx.x;
    if (idx >= 128 * ncols) return;
    int k = idx / ncols, j = idx % ncols;
    float v = (j < out) ? root[k * out + j]
                        : W[((j / out - 1) * 128 + k) * out + (j % out)];
    g_Bsp[idx] = __float2half_rn(v);
}

// ---------------- question projection ----------------
__global__ void k_q(const float* __restrict__ qe, const float* __restrict__ qnW,
                    const float* __restrict__ qnb) {
    __shared__ float sq[768];
    int g = blockIdx.x, j = threadIdx.x;
    for (int i = j; i < 768; i += 64) sq[i] = qe[g * 768 + i];
    __syncthreads();
    float acc = qnb[j];
    for (int k = 0; k < 768; k++) acc = fmaf(sq[k], qnW[k * 64 + j], acc);
    g_q[g * 64 + j] = fmaxf(acc, 0.0f);
}

// ---------------- CSR build ----------------
__global__ void k_count(const int* __restrict__ dst, const int* __restrict__ ea) {
    int e = blockIdx.x * blockDim.x + threadIdx.x;
    if (e >= EE) return;
    atomicAdd(&g_cnt[ea[e] * NN + dst[e]], 1);
}
__global__ void k_scan1() {
    int t = threadIdx.x;
    int i = blockIdx.x * 256 + t;
    int tot = 0;
    if (i < NN) {
#pragma unroll
        for (int r = 0; r < RR; r++) {
            int c = g_cnt[r * NN + i];
            tot += c;
            g_inv[i * 4 + r] = 1.0f / (float)max(c, 1);
        }
        g_deg[i] = tot;
    }
    __shared__ int s[256];
    s[t] = tot;
    __syncthreads();
    for (int d = 128; d; d >>= 1) {
        if (t < d) s[t] += s[t + d];
        __syncthreads();
    }
    if (t == 0) g_part[blockIdx.x] = s[0];
}
__global__ void k_scan2() {
    __shared__ int s[256];
    int t = threadIdx.x;
    int v = (t < 196) ? g_part[t] : 0;
    s[t] = v;
    __syncthreads();
    for (int d = 1; d < 256; d <<= 1) {
        int x = (t >= d) ? s[t - d] : 0;
        __syncthreads();
        s[t] += x;
        __syncthreads();
    }
    if (t < 196) g_part[t] = s[t] - v;
    if (t == 255) g_rowptr[NN] = s[255];
}
__global__ void k_scan3() {
    int t = threadIdx.x;
    int i = blockIdx.x * 256 + t;
    int v = (i < NN) ? g_deg[i] : 0;
    __shared__ int s[256];
    s[t] = v;
    __syncthreads();
    for (int d = 1; d < 256; d <<= 1) {
        int x = (t >= d) ? s[t - d] : 0;
        __syncthreads();
        s[t] += x;
        __syncthreads();
    }
    if (i < NN) {
        int off = g_part[blockIdx.x] + s[t] - v;
        g_rowptr[i] = off;
        g_fill[i] = off;
    }
}
__global__ void k_fill(const int* __restrict__ src, const int* __restrict__ dst,
                       const int* __restrict__ ea) {
    int e = blockIdx.x * blockDim.x + threadIdx.x;
    if (e >= EE) return;
    int d = dst[e];
    int pos = atomicAdd(&g_fill[d], 1);
    g_csr[pos] = src[e] | (ea[e] << 28);
}

// ---------------- GEMM: B-resident per CTA, A streamed double-buffered ----------------
// grid = (GX, nblocks). Each CTA: fixed 128-col B panel; strides M-tiles (64 rows).
#define AST 136   // 128 + 8 pad (halves)
#define BST 136
#define GEMM_SMEM ((2 * 64 * AST + 128 * BST) * 2)   // 34.8K + 34.8K = 69.6KB -> 3 CTA/SM

__global__ void __launch_bounds__(128, 3) k_gemm(const float* __restrict__ bias,
                                                 int out) {
    extern __shared__ __half smem[];
    __half* sA0 = smem;                    // [64][AST] x2
    __half* sB  = smem + 2 * 64 * AST;     // [128][BST]
    int t = threadIdx.x;
    int ncols = 5 * out;
    int n0 = blockIdx.y * 128;
    int GX = gridDim.x;

    // load B panel once (128 rows x 128 cols = 2048 uint4, 16 per thread)
    {
        uint32_t sbb = smem_u32(sB);
#pragma unroll
        for (int i = 0; i < 16; i++) {
            int idx = t + i * 128;
            int row = idx >> 4;
            int c8 = (idx & 15) * 8;
            cp_async16(sbb + (row * BST + c8) * 2, g_Bsp + (size_t)row * ncols + n0 + c8);
        }
        cp_commit();
    }

    // prefetch first A tile
    int mt = blockIdx.x;
    if (mt < MT) {
        __half* sA = sA0;
        uint32_t sab = smem_u32(sA);
#pragma unroll
        for (int i = 0; i < 8; i++) {
            int idx = t + i * 128;
            int row = idx >> 4;
            int c8 = (idx & 15) * 8;
            int grow = mt * 64 + row;
            if (grow < NN)
                cp_async16(sab + (row * AST + c8) * 2, g_Asp + (size_t)grow * 128 + c8);
            else
                *(uint4*)(sA + row * AST + c8) = make_uint4(0, 0, 0, 0);
        }
        cp_commit();
    }

    int w = t >> 5, lane = t & 31;
    int wm = (w & 1) * 32, wn = (w >> 1) * 64;
    int lr = lane & 15, lc = lane >> 4;
    int g = lane >> 2, tg = lane & 3;
    int pitchM = 4 * out;
    int buf = 0;

    for (; mt < MT; mt += GX) {
        int mnext = mt + GX;
        if (mnext < MT) {
            __half* sA = sA0 + (buf ^ 1) * 64 * AST;
            uint32_t sab = smem_u32(sA);
#pragma unroll
            for (int i = 0; i < 8; i++) {
                int idx = t + i * 128;
                int row = idx >> 4;
                int c8 = (idx & 15) * 8;
                int grow = mnext * 64 + row;
                if (grow < NN)
                    cp_async16(sab + (row * AST + c8) * 2, g_Asp + (size_t)grow * 128 + c8);
                else
                    *(uint4*)(sA + row * AST + c8) = make_uint4(0, 0, 0, 0);
            }
            cp_commit();
            cp_wait<1>();
        } else {
            cp_wait<0>();
        }
        __syncthreads();

        __half* sA = sA0 + buf * 64 * AST;
        int m0 = mt * 64;

        float acc[2][8][4];
#pragma unroll
        for (int mti = 0; mti < 2; mti++)
#pragma unroll
            for (int nt = 0; nt < 8; nt++)
#pragma unroll
                for (int i = 0; i < 4; i++) acc[mti][nt][i] = 0.0f;

#pragma unroll
        for (int kk = 0; kk < 8; kk++) {
            uint32_t b[4][4];
#pragma unroll
            for (int nh = 0; nh < 4; nh++)
                ldsm4t(b[nh], sB + (kk * 16 + lr) * BST + wn + nh * 16 + lc * 8);
            uint32_t a[2][4];
#pragma unroll
            for (int mti = 0; mti < 2; mti++)
                ldsm4(a[mti], sA + (wm + mti * 16 + lr) * AST + kk * 16 + lc * 8);
#pragma unroll
            for (int mti = 0; mti < 2; mti++)
#pragma unroll
                for (int nt = 0; nt < 8; nt++) {
                    int nh = nt >> 1, h = (nt & 1) * 2;
                    mma16816(acc[mti][nt], a[mti], b[nh][h], b[nh][h + 1]);
                }
        }

#pragma unroll
        for (int mti = 0; mti < 2; mti++) {
#pragma unroll
            for (int nt = 0; nt < 8; nt++) {
                int col = n0 + wn + nt * 8 + tg * 2;
                if (col >= ncols) continue;
                int r0 = m0 + wm + mti * 16 + g;
                int r1 = r0 + 8;
                if (col < out) {
                    float b0 = bias[col], b1 = bias[col + 1];
                    if (r0 < NN) {
                        g_Ys[(size_t)r0 * out + col]     = acc[mti][nt][0] + b0;
                        g_Ys[(size_t)r0 * out + col + 1] = acc[mti][nt][1] + b1;
                    }
                    if (r1 < NN) {
                        g_Ys[(size_t)r1 * out + col]     = acc[mti][nt][2] + b0;
                        g_Ys[(size_t)r1 * out + col + 1] = acc[mti][nt][3] + b1;
                    }
                } else {
                    int mc = col - out;
                    if (r0 < NN)
                        *(__half2*)(g_Ym + (size_t)r0 * pitchM + mc) =
                            __floats2half2_rn(acc[mti][nt][0], acc[mti][nt][1]);
                    if (r1 < NN)
                        *(__half2*)(g_Ym + (size_t)r1 * pitchM + mc) =
                            __floats2half2_rn(acc[mti][nt][2], acc[mti][nt][3]);
                }
            }
        }
        __syncthreads();   // everyone done reading sA[buf] before it's refilled
        buf ^= 1;
    }
}

// ---------------- pull aggregation: one warp per node; fused relu (+q) epilogue ----------------
template <int OUT, int MODE, int QF>
__global__ void __launch_bounds__(256) k_agg(float* __restrict__ Optr,
                                             const int* __restrict__ batch) {
    int w = (blockIdx.x * 256 + threadIdx.x) >> 5;
    if (w >= NN) return;
    int lane = threadIdx.x & 31;
    constexpr int V = OUT / 32;
    constexpr int PITCH = 4 * OUT;
    int start = g_rowptr[w], end = g_rowptr[w + 1];
    float4 iv4 = *(const float4*)(g_inv + w * 4);

    float acc[V];
    {
        const float* sp = g_Ys + (size_t)w * OUT + lane * V;
        if constexpr (V == 4) {
            float4 s = *(const float4*)sp;
            acc[0] = s.x; acc[1] = s.y; acc[2] = s.z; acc[3] = s.w;
        } else {
            float2 s = *(const float2*)sp;
            acc[0] = s.x; acc[1] = s.y;
        }
    }

    int e = start;
    for (; e + 4 <= end; e += 4) {
        int u0 = g_csr[e], u1 = g_csr[e + 1], u2 = g_csr[e + 2], u3 = g_csr[e + 3];
        int s0 = u0 & 0x0FFFFFFF, r0 = ((unsigned)u0) >> 28;
        int s1 = u1 & 0x0FFFFFFF, r1 = ((unsigned)u1) >> 28;
        int s2 = u2 & 0x0FFFFFFF, r2 = ((unsigned)u2) >> 28;
        int s3 = u3 & 0x0FFFFFFF, r3 = ((unsigned)u3) >> 28;
        const __half* p0 = g_Ym + (size_t)s0 * PITCH + r0 * OUT + lane * V;
        const __half* p1 = g_Ym + (size_t)s1 * PITCH + r1 * OUT + lane * V;
        const __half* p2 = g_Ym + (size_t)s2 * PITCH + r2 * OUT + lane * V;
        const __half* p3 = g_Ym + (size_t)s3 * PITCH + r3 * OUT + lane * V;
        float i0 = pick4(iv4, r0), i1 = pick4(iv4, r1);
        float i2 = pick4(iv4, r2), i3 = pick4(iv4, r3);
        if constexpr (V == 4) {
            uint2 w0 = *(const uint2*)p0;
            uint2 w1 = *(const uint2*)p1;
            uint2 w2 = *(const uint2*)p2;
            uint2 w3 = *(const uint2*)p3;
            float2 a0 = __half22float2(*(__half2*)&w0.x), a1 = __half22float2(*(__half2*)&w0.y);
            float2 b0 = __half22float2(*(__half2*)&w1.x), b1 = __half22float2(*(__half2*)&w1.y);
            float2 c0 = __half22float2(*(__half2*)&w2.x), c1 = __half22float2(*(__half2*)&w2.y);
            float2 d0 = __half22float2(*(__half2*)&w3.x), d1 = __half22float2(*(__half2*)&w3.y);
            acc[0] += a0.x * i0; acc[1] += a0.y * i0; acc[2] += a1.x * i0; acc[3] += a1.y * i0;
            acc[0] += b0.x * i1; acc[1] += b0.y * i1; acc[2] += b1.x * i1; acc[3] += b1.y * i1;
            acc[0] += c0.x * i2; acc[1] += c0.y * i2; acc[2] += c1.x * i2; acc[3] += c1.y * i2;
            acc[0] += d0.x * i3; acc[1] += d0.y * i3; acc[2] += d1.x * i3; acc[3] += d1.y * i3;
        } else {
            uint32_t w0 = *(const uint32_t*)p0;
            uint32_t w1 = *(const uint32_t*)p1;
            uint32_t w2 = *(const uint32_t*)p2;
            uint32_t w3 = *(const uint32_t*)p3;
            float2 a0 = __half22float2(*(__half2*)&w0);
            float2 b0 = __half22float2(*(__half2*)&w1);
            float2 c0 = __half22float2(*(__half2*)&w2);
            float2 d0 = __half22float2(*(__half2*)&w3);
            acc[0] += a0.x * i0; acc[1] += a0.y * i0;
            acc[0] += b0.x * i1; acc[1] += b0.y * i1;
            acc[0] += c0.x * i2; acc[1] += c0.y * i2;
            acc[0] += d0.x * i3; acc[1] += d0.y * i3;
        }
    }
    for (; e < end; e++) {
        int u0 = g_csr[e];
        int s0 = u0 & 0x0FFFFFFF, r0 = ((unsigned)u0) >> 28;
        const __half* p0 = g_Ym + (size_t)s0 * PITCH + r0 * OUT + lane * V;
        float i0 = pick4(iv4, r0);
        if constexpr (V == 4) {
            uint2 w0 = *(const uint2*)p0;
            float2 a0 = __half22float2(*(__half2*)&w0.x);
            float2 a1 = __half22float2(*(__half2*)&w0.y);
            acc[0] += a0.x * i0; acc[1] += a0.y * i0;
            acc[2] += a1.x * i0; acc[3] += a1.y * i0;
        } else {
            uint32_t w0 = *(const uint32_t*)p0;
            float2 a0 = __half22float2(*(__half2*)&w0);
            acc[0] += a0.x * i0; acc[1] += a0.y * i0;
        }
    }

    if constexpr (MODE == 0) {
        union { __half h[V]; uint2 u2; uint32_t u1; } ph;
#pragma unroll
        for (int j = 0; j < V; j++)
            ph.h[j] = __float2half_rn(fmaxf(acc[j], 0.0f));
        __half* base = g_Asp + (size_t)w * 128 + lane * V;
        if constexpr (V == 4) *(uint2*)base = ph.u2;
        else                  *(uint32_t*)base = ph.u1;
        if constexpr (QF) {
            int b = batch[w];
            __half2 hh;
            hh.x = __float2half_rn(g_q[b * 64 + lane * 2]);
            hh.y = __float2half_rn(g_q[b * 64 + lane * 2 + 1]);
            *(__half2*)(g_Asp + (size_t)w * 128 + 64 + lane * 2) = hh;
        }
    } else {
        float* op = Optr + (size_t)w * OUT + lane * V;
        if constexpr (V == 4) {
            float4 r; r.x = acc[0]; r.y = acc[1]; r.z = acc[2]; r.w = acc[3];
            *(float4*)op = r;
        } else {
            float2 r; r.x = acc[0]; r.y = acc[1];
            *(float2*)op = r;
        }
    }
}

// ---------------- host orchestration ----------------
extern "C" void kernel_launch(void* const* d_in, const int* in_sizes, int n_in,
                              void* d_out, int out_size) {
    const float* x     = (const float*)d_in[0];
    const int*   ei    = (const int*)d_in[1];
    const int*   ea    = (const int*)d_in[2];
    const int*   batch = (const int*)d_in[3];
    const float* qe    = (const float*)d_in[4];
    const float* qnW   = (const float*)d_in[5];
    const float* qnb   = (const float*)d_in[6];
    const float* W0 = (const float*)d_in[7],  *root0 = (const float*)d_in[8],  *b0 = (const float*)d_in[9];
    const float* W1 = (const float*)d_in[10], *root1 = (const float*)d_in[11], *b1 = (const float*)d_in[12];
    const float* W2 = (const float*)d_in[13], *root2 = (const float*)d_in[14], *b2 = (const float*)d_in[15];
    const float* W3 = (const float*)d_in[16], *root3 = (const float*)d_in[17], *b3 = (const float*)d_in[18];
    float* out = (float*)d_out;

    const int* src = ei;
    const int* dst = ei + EE;

    cudaFuncSetAttribute(k_gemm, cudaFuncAttributeMaxDynamicSharedMemorySize, GEMM_SMEM);

    const int AGG_G = (NN * 32 + 255) / 256;  // 6250
    const dim3 G64(148, 3);    // out=64: 444 CTAs, ~5.3 M-tiles each
    const dim3 G128(88, 5);    // out=128: 440 CTAs, ~8.9 M-tiles each

    // k_gemm is launch #4 so ncu -s captures it.
    k_prepA0<<<(NN * 128 + 255) / 256, 256>>>(x);              // 1 (also zeroes g_cnt)
    k_prepB<<<(128 * 320 + 255) / 256, 256>>>(root0, W0, 64);  // 2
    k_q<<<GG, 64>>>(qe, qnW, qnb);                             // 3
    k_gemm<<<G64, 128, GEMM_SMEM>>>(b0, 64);                   // 4 (profiled)
    k_count<<<(EE + 255) / 256, 256>>>(dst, ea);               // 5
    k_scan1<<<196, 256>>>();                                   // 6
    k_scan2<<<1, 256>>>();                                     // 7
    k_scan3<<<196, 256>>>();                                   // 8
    k_fill<<<(EE + 255) / 256, 256>>>(src, dst, ea);           // 9

    // Layer 0 aggregation (+ fused q[batch] fill)
    k_agg<64, 0, 1><<<AGG_G, 256>>>(nullptr, batch);

    // Layer 1: in=128, out=128
    k_prepB<<<(128 * 640 + 255) / 256, 256>>>(root1, W1, 128);
    k_gemm<<<G128, 128, GEMM_SMEM>>>(b1, 128);
    k_agg<128, 0, 0><<<AGG_G, 256>>>(nullptr, nullptr);

    // Layer 2: in=128, out=128
    k_prepB<<<(128 * 640 + 255) / 256, 256>>>(root2, W2, 128);
    k_gemm<<<G128, 128, GEMM_SMEM>>>(b2, 128);
    k_agg<128, 0, 0><<<AGG_G, 256>>>(nullptr, nullptr);

    // Layer 3: in=128, out=64 -> d_out
    k_prepB<<<(128 * 320 + 255) / 256, 256>>>(root3, W3, 64);
    k_gemm<<<G64, 128, GEMM_SMEM>>>(b3, 64);
    k_agg<64, 1, 0><<<AGG_G, 256>>>(out, nullptr);
}

// round 9
// speedup vs baseline: 1.4971x; 1.4971x over previous
#include <cuda_runtime.h>
#include <cuda_bf16.h>
#include <cuda_fp16.h>
#include <cstdint>

#define NN 50000
#define EE 800000
#define RR 4
#define GG 16

// ---------------- scratch (device globals; no allocation) ----------------
__device__ float   g_Ys[NN * 128];          // self+bias, fp32 [N][out]
__device__ __half  g_Ym[NN * 512];          // messages fp16 [N][4*out] (L2-resident)
__device__ __half  g_Asp[NN * 128];         // activations fp16 [N][128]
__device__ __half  g_Bsp[128 * 640];        // weights fp16, row-major [k][5*out]
__device__ float   g_q[GG * 64];
__device__ int     g_cnt[RR * NN];          // ALWAYS zero at call entry (scan1 re-zeroes)
__device__ float   g_inv[NN * 4];
__device__ int     g_deg[NN];
__device__ int     g_part[256];
__device__ int     g_rowptr[NN + 1];
__device__ int     g_fill[NN];
__device__ int     g_csr[EE];               // src | (rel<<28)

// ---------------- helpers ----------------
__device__ __forceinline__ uint32_t smem_u32(const void* p) {
    return (uint32_t)__cvta_generic_to_shared(p);
}
__device__ __forceinline__ void ldsm4(uint32_t* d, const __half* p) {
    uint32_t a = smem_u32(p);
    asm volatile("ldmatrix.sync.aligned.m8n8.x4.shared.b16 {%0,%1,%2,%3}, [%4];"
                 : "=r"(d[0]), "=r"(d[1]), "=r"(d[2]), "=r"(d[3]) : "r"(a));
}
__device__ __forceinline__ void ldsm4t(uint32_t* d, const __half* p) {
    uint32_t a = smem_u32(p);
    asm volatile("ldmatrix.sync.aligned.m8n8.x4.trans.shared.b16 {%0,%1,%2,%3}, [%4];"
                 : "=r"(d[0]), "=r"(d[1]), "=r"(d[2]), "=r"(d[3]) : "r"(a));
}
__device__ __forceinline__ void mma16816(float* c, const uint32_t* a, uint32_t b0, uint32_t b1) {
    asm volatile(
        "mma.sync.aligned.m16n8k16.row.col.f32.f16.f16.f32 "
        "{%0,%1,%2,%3}, {%4,%5,%6,%7}, {%8,%9}, {%0,%1,%2,%3};"
        : "+f"(c[0]), "+f"(c[1]), "+f"(c[2]), "+f"(c[3])
        : "r"(a[0]), "r"(a[1]), "r"(a[2]), "r"(a[3]), "r"(b0), "r"(b1));
}
__device__ __forceinline__ void cp_async16(uint32_t smem_addr, const void* gptr) {
    asm volatile("cp.async.cg.shared.global [%0], [%1], 16;" :: "r"(smem_addr), "l"(gptr));
}
__device__ __forceinline__ void cp_commit() {
    asm volatile("cp.async.commit_group;" ::: "memory");
}
template <int N>
__device__ __forceinline__ void cp_wait() {
    asm volatile("cp.async.wait_group %0;" :: "n"(N) : "memory");
}
__device__ __forceinline__ float pick4(float4 v, int r) {
    return r == 0 ? v.x : (r == 1 ? v.y : (r == 2 ? v.z : v.w));
}

// ---------------- prepB body (shared by mega kernels) ----------------
__device__ __forceinline__ void prepB_body(int idx, const float* __restrict__ root,
                                           const float* __restrict__ W, int out) {
    int ncols = 5 * out;
    if (idx >= 128 * ncols) return;
    int k = idx / ncols, j = idx % ncols;
    float v = (j < out) ? root[k * out + j]
                        : W[((j / out - 1) * 128 + k) * out + (j % out)];
    g_Bsp[idx] = __float2half_rn(v);
}

// ---------------- mega1: prepA0 + edge count + prepB0 + q projection ----------------
#define PA_BLK 25000    // NN*128/256
#define CNT_BLK 3125    // EE/256
#define PB0_BLK 160     // 128*320/256
#define Q_BLK 16
__global__ void __launch_bounds__(256) k_mega1(
    const float* __restrict__ x, const int* __restrict__ dst, const int* __restrict__ ea,
    const float* __restrict__ root0, const float* __restrict__ W0,
    const float* __restrict__ qe, const float* __restrict__ qnW, const float* __restrict__ qnb) {
    int b = blockIdx.x, t = threadIdx.x;
    if (b < PA_BLK) {
        int idx = b * 256 + t;
        g_Asp[idx] = __float2half_rn(x[idx]);
    } else if (b < PA_BLK + CNT_BLK) {
        int e = (b - PA_BLK) * 256 + t;
        atomicAdd(&g_cnt[ea[e] * NN + dst[e]], 1);
    } else if (b < PA_BLK + CNT_BLK + PB0_BLK) {
        prepB_body((b - PA_BLK - CNT_BLK) * 256 + t, root0, W0, 64);
    } else {
        __shared__ float sq[768];
        int g = b - PA_BLK - CNT_BLK - PB0_BLK;
        for (int i = t; i < 768; i += 256) sq[i] = qe[g * 768 + i];
        __syncthreads();
        if (t < 64) {
            float acc = qnb[t];
            for (int k = 0; k < 768; k++) acc = fmaf(sq[k], qnW[k * 64 + t], acc);
            g_q[g * 64 + t] = fmaxf(acc, 0.0f);
        }
    }
}

// ---------------- CSR scans (scan1 re-zeroes g_cnt for next call) ----------------
__global__ void k_scan1() {
    int t = threadIdx.x;
    int i = blockIdx.x * 256 + t;
    int tot = 0;
    if (i < NN) {
#pragma unroll
        for (int r = 0; r < RR; r++) {
            int c = g_cnt[r * NN + i];
            g_cnt[r * NN + i] = 0;            // restore zero for next invocation
            tot += c;
            g_inv[i * 4 + r] = 1.0f / (float)max(c, 1);
        }
        g_deg[i] = tot;
    }
    __shared__ int s[256];
    s[t] = tot;
    __syncthreads();
    for (int d = 128; d; d >>= 1) {
        if (t < d) s[t] += s[t + d];
        __syncthreads();
    }
    if (t == 0) g_part[blockIdx.x] = s[0];
}
__global__ void k_scan2() {
    __shared__ int s[256];
    int t = threadIdx.x;
    int v = (t < 196) ? g_part[t] : 0;
    s[t] = v;
    __syncthreads();
    for (int d = 1; d < 256; d <<= 1) {
        int x = (t >= d) ? s[t - d] : 0;
        __syncthreads();
        s[t] += x;
        __syncthreads();
    }
    if (t < 196) g_part[t] = s[t] - v;
    if (t == 255) g_rowptr[NN] = s[255];
}
__global__ void k_scan3() {
    int t = threadIdx.x;
    int i = blockIdx.x * 256 + t;
    int v = (i < NN) ? g_deg[i] : 0;
    __shared__ int s[256];
    s[t] = v;
    __syncthreads();
    for (int d = 1; d < 256; d <<= 1) {
        int x = (t >= d) ? s[t - d] : 0;
        __syncthreads();
        s[t] += x;
        __syncthreads();
    }
    if (i < NN) {
        int off = g_part[blockIdx.x] + s[t] - v;
        g_rowptr[i] = off;
        g_fill[i] = off;
    }
}
__global__ void k_fill(const int* __restrict__ src, const int* __restrict__ dst,
                       const int* __restrict__ ea) {
    int e = blockIdx.x * blockDim.x + threadIdx.x;
    if (e >= EE) return;
    int d = dst[e];
    int pos = atomicAdd(&g_fill[d], 1);
    g_csr[pos] = src[e] | (ea[e] << 28);
}

// ---------------- GEMM (R7 version): 64-row CTAs, 128 thr, warp 32x64, K=128 ----------------
#define AST 136   // 128 + 8 pad (halves)
#define BST 136
#define GEMM_SMEM ((64 * AST + 128 * BST) * 2)   // 52.2KB -> 4 CTA/SM

__global__ void __launch_bounds__(128, 4) k_gemm(const float* __restrict__ bias,
                                                 int out, int niter) {
    extern __shared__ __half smem[];
    __half* sA = smem;                 // [64][AST]
    __half* sB = smem + 64 * AST;      // [128][BST]
    int m0 = blockIdx.x * 64;
    int t = threadIdx.x;
    int ncols = 5 * out;

    // load A tile (64 x 128 halves = 1024 uint4, 8 per thread)
#pragma unroll
    for (int i = 0; i < 8; i++) {
        int idx = t + i * 128;
        int row = idx >> 4;
        int c8 = (idx & 15) * 8;
        int grow = m0 + row;
        uint4 val = make_uint4(0, 0, 0, 0);
        if (grow < NN) val = *(const uint4*)(g_Asp + (size_t)grow * 128 + c8);
        *(uint4*)(sA + row * AST + c8) = val;
    }

    int w = t >> 5, lane = t & 31;
    int wm = (w & 1) * 32, wn = (w >> 1) * 64;
    int lr = lane & 15, lc = lane >> 4;
    int g = lane >> 2, tg = lane & 3;
    int pitchM = 4 * out;

    for (int nb = 0; nb < niter; nb++) {
        int n0 = nb * 128;
        __syncthreads();
        {
            uint32_t sbb = smem_u32(sB);
#pragma unroll
            for (int i = 0; i < 16; i++) {
                int idx = t + i * 128;
                int row = idx >> 4;
                int c8 = (idx & 15) * 8;
                cp_async16(sbb + (row * BST + c8) * 2, g_Bsp + (size_t)row * ncols + n0 + c8);
            }
            cp_commit();
            cp_wait<0>();
        }
        __syncthreads();

        float acc[2][8][4];
#pragma unroll
        for (int mt = 0; mt < 2; mt++)
#pragma unroll
            for (int nt = 0; nt < 8; nt++)
#pragma unroll
                for (int i = 0; i < 4; i++) acc[mt][nt][i] = 0.0f;

#pragma unroll
        for (int kk = 0; kk < 8; kk++) {
            uint32_t b[4][4];
#pragma unroll
            for (int nh = 0; nh < 4; nh++)
                ldsm4t(b[nh], sB + (kk * 16 + lr) * BST + wn + nh * 16 + lc * 8);
            uint32_t a[2][4];
#pragma unroll
            for (int mt = 0; mt < 2; mt++)
                ldsm4(a[mt], sA + (wm + mt * 16 + lr) * AST + kk * 16 + lc * 8);
#pragma unroll
            for (int mt = 0; mt < 2; mt++)
#pragma unroll
                for (int nt = 0; nt < 8; nt++) {
                    int nh = nt >> 1, h = (nt & 1) * 2;
                    mma16816(acc[mt][nt], a[mt], b[nh][h], b[nh][h + 1]);
                }
        }

#pragma unroll
        for (int mt = 0; mt < 2; mt++) {
#pragma unroll
            for (int nt = 0; nt < 8; nt++) {
                int col = n0 + wn + nt * 8 + tg * 2;
                if (col >= ncols) continue;
                int r0 = m0 + wm + mt * 16 + g;
                int r1 = r0 + 8;
                if (col < out) {
                    float b0 = bias[col], b1 = bias[col + 1];
                    if (r0 < NN) {
                        g_Ys[(size_t)r0 * out + col]     = acc[mt][nt][0] + b0;
                        g_Ys[(size_t)r0 * out + col + 1] = acc[mt][nt][1] + b1;
                    }
                    if (r1 < NN) {
                        g_Ys[(size_t)r1 * out + col]     = acc[mt][nt][2] + b0;
                        g_Ys[(size_t)r1 * out + col + 1] = acc[mt][nt][3] + b1;
                    }
                } else {
                    int mc = col - out;
                    if (r0 < NN)
                        *(__half2*)(g_Ym + (size_t)r0 * pitchM + mc) =
                            __floats2half2_rn(acc[mt][nt][0], acc[mt][nt][1]);
                    if (r1 < NN)
                        *(__half2*)(g_Ym + (size_t)r1 * pitchM + mc) =
                            __floats2half2_rn(acc[mt][nt][2], acc[mt][nt][3]);
                }
            }
        }
    }
}

// ---------------- aggregation (+ fused next-layer prepB blocks) ----------------
#define AGG_BLK 6250    // NN*32/256 warps-per-node blocks
// MODE 0: relu(total) fp16 -> g_Asp ; MODE 1: total fp32 -> Optr
// QF: also fill q[batch] into Asp cols [64:128)
// NXT: next layer's out (0 = none); blocks [AGG_BLK, ...) do prepB(root,W,NXT)
template <int OUT, int MODE, int QF, int NXT>
__global__ void __launch_bounds__(256) k_agg(float* __restrict__ Optr,
                                             const int* __restrict__ batch,
                                             const float* __restrict__ root,
                                             const float* __restrict__ W) {
    if (NXT > 0 && blockIdx.x >= AGG_BLK) {
        prepB_body((blockIdx.x - AGG_BLK) * 256 + threadIdx.x, root, W, NXT);
        return;
    }
    int w = (blockIdx.x * 256 + threadIdx.x) >> 5;
    if (w >= NN) return;
    int lane = threadIdx.x & 31;
    constexpr int V = OUT / 32;
    constexpr int PITCH = 4 * OUT;
    int start = g_rowptr[w], end = g_rowptr[w + 1];
    float4 iv4 = *(const float4*)(g_inv + w * 4);

    float acc[V];
    {
        const float* sp = g_Ys + (size_t)w * OUT + lane * V;
        if constexpr (V == 4) {
            float4 s = *(const float4*)sp;
            acc[0] = s.x; acc[1] = s.y; acc[2] = s.z; acc[3] = s.w;
        } else {
            float2 s = *(const float2*)sp;
            acc[0] = s.x; acc[1] = s.y;
        }
    }

    int e = start;
    for (; e + 4 <= end; e += 4) {
        int u0 = g_csr[e], u1 = g_csr[e + 1], u2 = g_csr[e + 2], u3 = g_csr[e + 3];
        int s0 = u0 & 0x0FFFFFFF, r0 = ((unsigned)u0) >> 28;
        int s1 = u1 & 0x0FFFFFFF, r1 = ((unsigned)u1) >> 28;
        int s2 = u2 & 0x0FFFFFFF, r2 = ((unsigned)u2) >> 28;
        int s3 = u3 & 0x0FFFFFFF, r3 = ((unsigned)u3) >> 28;
        const __half* p0 = g_Ym + (size_t)s0 * PITCH + r0 * OUT + lane * V;
        const __half* p1 = g_Ym + (size_t)s1 * PITCH + r1 * OUT + lane * V;
        const __half* p2 = g_Ym + (size_t)s2 * PITCH + r2 * OUT + lane * V;
        const __half* p3 = g_Ym + (size_t)s3 * PITCH + r3 * OUT + lane * V;
        float i0 = pick4(iv4, r0), i1 = pick4(iv4, r1);
        float i2 = pick4(iv4, r2), i3 = pick4(iv4, r3);
        if constexpr (V == 4) {
            uint2 w0 = *(const uint2*)p0;
            uint2 w1 = *(const uint2*)p1;
            uint2 w2 = *(const uint2*)p2;
            uint2 w3 = *(const uint2*)p3;
            float2 a0 = __half22float2(*(__half2*)&w0.x), a1 = __half22float2(*(__half2*)&w0.y);
            float2 b0 = __half22float2(*(__half2*)&w1.x), b1 = __half22float2(*(__half2*)&w1.y);
            float2 c0 = __half22float2(*(__half2*)&w2.x), c1 = __half22float2(*(__half2*)&w2.y);
            float2 d0 = __half22float2(*(__half2*)&w3.x), d1 = __half22float2(*(__half2*)&w3.y);
            acc[0] += a0.x * i0; acc[1] += a0.y * i0; acc[2] += a1.x * i0; acc[3] += a1.y * i0;
            acc[0] += b0.x * i1; acc[1] += b0.y * i1; acc[2] += b1.x * i1; acc[3] += b1.y * i1;
            acc[0] += c0.x * i2; acc[1] += c0.y * i2; acc[2] += c1.x * i2; acc[3] += c1.y * i2;
            acc[0] += d0.x * i3; acc[1] += d0.y * i3; acc[2] += d1.x * i3; acc[3] += d1.y * i3;
        } else {
            uint32_t w0 = *(const uint32_t*)p0;
            uint32_t w1 = *(const uint32_t*)p1;
            uint32_t w2 = *(const uint32_t*)p2;
            uint32_t w3 = *(const uint32_t*)p3;
            float2 a0 = __half22float2(*(__half2*)&w0);
            float2 b0 = __half22float2(*(__half2*)&w1);
            float2 c0 = __half22float2(*(__half2*)&w2);
            float2 d0 = __half22float2(*(__half2*)&w3);
            acc[0] += a0.x * i0; acc[1] += a0.y * i0;
            acc[0] += b0.x * i1; acc[1] += b0.y * i1;
            acc[0] += c0.x * i2; acc[1] += c0.y * i2;
            acc[0] += d0.x * i3; acc[1] += d0.y * i3;
        }
    }
    for (; e < end; e++) {
        int u0 = g_csr[e];
        int s0 = u0 & 0x0FFFFFFF, r0 = ((unsigned)u0) >> 28;
        const __half* p0 = g_Ym + (size_t)s0 * PITCH + r0 * OUT + lane * V;
        float i0 = pick4(iv4, r0);
        if constexpr (V == 4) {
            uint2 w0 = *(const uint2*)p0;
            float2 a0 = __half22float2(*(__half2*)&w0.x);
            float2 a1 = __half22float2(*(__half2*)&w0.y);
            acc[0] += a0.x * i0; acc[1] += a0.y * i0;
            acc[2] += a1.x * i0; acc[3] += a1.y * i0;
        } else {
            uint32_t w0 = *(const uint32_t*)p0;
            float2 a0 = __half22float2(*(__half2*)&w0);
            acc[0] += a0.x * i0; acc[1] += a0.y * i0;
        }
    }

    if constexpr (MODE == 0) {
        union { __half h[V]; uint2 u2; uint32_t u1; } ph;
#pragma unroll
        for (int j = 0; j < V; j++)
            ph.h[j] = __float2half_rn(fmaxf(acc[j], 0.0f));
        __half* base = g_Asp + (size_t)w * 128 + lane * V;
        if constexpr (V == 4) *(uint2*)base = ph.u2;
        else                  *(uint32_t*)base = ph.u1;
        if constexpr (QF) {
            int b = batch[w];
            __half2 hh;
            hh.x = __float2half_rn(g_q[b * 64 + lane * 2]);
            hh.y = __float2half_rn(g_q[b * 64 + lane * 2 + 1]);
            *(__half2*)(g_Asp + (size_t)w * 128 + 64 + lane * 2) = hh;
        }
    } else {
        float* op = Optr + (size_t)w * OUT + lane * V;
        if constexpr (V == 4) {
            float4 r; r.x = acc[0]; r.y = acc[1]; r.z = acc[2]; r.w = acc[3];
            *(float4*)op = r;
        } else {
            float2 r; r.x = acc[0]; r.y = acc[1];
            *(float2*)op = r;
        }
    }
}

// ---------------- host orchestration ----------------
extern "C" void kernel_launch(void* const* d_in, const int* in_sizes, int n_in,
                              void* d_out, int out_size) {
    const float* x     = (const float*)d_in[0];
    const int*   ei    = (const int*)d_in[1];
    const int*   ea    = (const int*)d_in[2];
    const int*   batch = (const int*)d_in[3];
    const float* qe    = (const float*)d_in[4];
    const float* qnW   = (const float*)d_in[5];
    const float* qnb   = (const float*)d_in[6];
    const float* W0 = (const float*)d_in[7],  *root0 = (const float*)d_in[8],  *b0 = (const float*)d_in[9];
    const float* W1 = (const float*)d_in[10], *root1 = (const float*)d_in[11], *b1 = (const float*)d_in[12];
    const float* W2 = (const float*)d_in[13], *root2 = (const float*)d_in[14], *b2 = (const float*)d_in[15];
    const float* W3 = (const float*)d_in[16], *root3 = (const float*)d_in[17], *b3 = (const float*)d_in[18];
    float* out = (float*)d_out;

    const int* src = ei;
    const int* dst = ei + EE;

    cudaFuncSetAttribute(k_gemm, cudaFuncAttributeMaxDynamicSharedMemorySize, GEMM_SMEM);

    const int MG = 782;                       // ceil(50000/64)

    // 1: fused prepA0 + count + prepB0 + q
    k_mega1<<<PA_BLK + CNT_BLK + PB0_BLK + Q_BLK, 256>>>(x, dst, ea, root0, W0, qe, qnW, qnb);
    k_scan1<<<196, 256>>>();                                   // 2 (re-zeroes g_cnt)
    k_scan2<<<1, 256>>>();                                     // 3
    k_gemm<<<MG, 128, GEMM_SMEM>>>(b0, 64, 3);                 // 4 (profiled)
    k_scan3<<<196, 256>>>();                                   // 5
    k_fill<<<(EE + 255) / 256, 256>>>(src, dst, ea);           // 6

    // 7: agg layer 0 (+q fill) + prepB1
    k_agg<64, 0, 1, 128><<<AGG_BLK + 320, 256>>>(nullptr, batch, root1, W1);
    // 8: layer 1 GEMM
    k_gemm<<<MG, 128, GEMM_SMEM>>>(b1, 128, 5);
    // 9: agg layer 1 + prepB2
    k_agg<128, 0, 0, 128><<<AGG_BLK + 320, 256>>>(nullptr, nullptr, root2, W2);
    // 10: layer 2 GEMM
    k_gemm<<<MG, 128, GEMM_SMEM>>>(b2, 128, 5);
    // 11: agg layer 2 + prepB3
    k_agg<128, 0, 0, 64><<<AGG_BLK + 160, 256>>>(nullptr, nullptr, root3, W3);
    // 12: layer 3 GEMM
    k_gemm<<<MG, 128, GEMM_SMEM>>>(b3, 64, 3);
    // 13: final aggregation -> d_out
    k_agg<64, 1, 0, 0><<<AGG_BLK, 256>>>(out, nullptr, nullptr, nullptr);
}